// round 17
// baseline (speedup 1.0000x reference)
#include <cuda_runtime.h>
#include <cuda_fp16.h>
#include <mma.h>
#include <math.h>

using namespace nvcuda;

// GATv2 (L=3, H=4, C=16, D=64), N=100000, E=1280000 (+N self loops).
// R17:
//  - launch order gemm+hist(0), scan1(1), csr2(2), agg(3) -> ncu idx3 = agg.
//  - k_csr2 fuses degscan (per-block smem scan of the 512-bin histogram),
//    block-aggregated degscatter, and the edge scatter into one grid.
//  - agg inner chunk fully unrolled (8 predicated batched LDG.128 -> MLP 8).

#define NNODES 100000
#define NEDGES 1280000
#define DD 64
#define XH_LD 72
#define W_LD 136
#define SCAN_BLK 512
#define SCAN_ELEM 8
#define SCAN_TILE (SCAN_BLK * SCAN_ELEM)  // 4096

__device__ __align__(128) __half g_xlh[(NNODES + 128) * DD];
__device__ __align__(128) __half g_xrh[(NNODES + 128) * DD];
__device__ __align__(16) float g_b0[NNODES * DD];
__device__ __align__(16) float g_b1[NNODES * DD];
__device__ int g_cnt[NNODES];      // zero at load; scan1 re-zeroes after reading
__device__ int g_ofs[NNODES];
__device__ int g_rowptr[NNODES + 1];
__device__ int g_pre[32];          // zeroed by layer-0 gemm each replay
__device__ int g_ssrc[NEDGES];
__device__ int g_perm[NNODES];
__device__ int g_dhist[512];       // zeroed by layer-0 gemm each replay
__device__ int g_dbase[512];       // zeroed by layer-0 gemm each replay

// ---------------------------------------------------------------------------
// Tensor-core GEMM: [64 nodes] x [128 cols] per block, 8 warps, 32x32/warp.
// Layer 0 (do_csr): zero g_pre/g_dhist/g_dbase + histogram dst into g_cnt.
// ---------------------------------------------------------------------------
__global__ __launch_bounds__(256) void k_gemm(const float* __restrict__ x,
                                              const float* __restrict__ Wl,
                                              const float* __restrict__ Wr,
                                              int n,
                                              const int* __restrict__ ei,
                                              int E, int do_csr) {
    extern __shared__ char smraw[];
    __half* xh = (__half*)smraw;                          // [64][XH_LD]
    __half* wh = (__half*)(smraw + 64 * XH_LD * 2);       // [64][W_LD]

    int tid = threadIdx.x;
    int nodeBase = blockIdx.x * 64;

    if (do_csr) {
        if (blockIdx.x == 0) {
            if (tid < 32) g_pre[tid] = 0;
            g_dhist[tid] = 0; g_dhist[tid + 256] = 0;
            g_dbase[tid] = 0; g_dbase[tid + 256] = 0;
        }
        int stride = gridDim.x * blockDim.x;
        for (int e = blockIdx.x * blockDim.x + tid; e < E; e += stride)
            atomicAdd(&g_cnt[ei[E + e]], 1);
    }

    for (int g = tid; g < 1024; g += 256) {
        int row = g >> 4;
        int c4 = (g & 15) << 2;
        int gn = nodeBase + row;
        float4 v = (gn < n) ? *(const float4*)&x[(size_t)gn * DD + c4]
                            : make_float4(0.f, 0.f, 0.f, 0.f);
        __half2 h0 = __floats2half2_rn(v.x, v.y);
        __half2 h1 = __floats2half2_rn(v.z, v.w);
        uint2 pk;
        pk.x = *(unsigned*)&h0;
        pk.y = *(unsigned*)&h1;
        *(uint2*)&xh[row * XH_LD + c4] = pk;
    }
    for (int g = tid; g < 2048; g += 256) {
        int k = g >> 5;
        int c4 = (g & 31) << 2;
        float4 v = (c4 < 64) ? *(const float4*)&Wl[k * 64 + c4]
                             : *(const float4*)&Wr[k * 64 + (c4 - 64)];
        __half2 h0 = __floats2half2_rn(v.x, v.y);
        __half2 h1 = __floats2half2_rn(v.z, v.w);
        uint2 pk;
        pk.x = *(unsigned*)&h0;
        pk.y = *(unsigned*)&h1;
        *(uint2*)&wh[k * W_LD + c4] = pk;
    }
    __syncthreads();

    int warp = tid >> 5;
    int wr = warp >> 2;
    int wc = warp & 3;

    wmma::fragment<wmma::accumulator, 16, 16, 16, __half> cf[2][2];
#pragma unroll
    for (int i = 0; i < 2; i++)
#pragma unroll
        for (int j = 0; j < 2; j++)
            wmma::fill_fragment(cf[i][j], __float2half(0.f));

#pragma unroll
    for (int kk = 0; kk < 64; kk += 16) {
        wmma::fragment<wmma::matrix_a, 16, 16, 16, __half, wmma::row_major> af[2];
        wmma::fragment<wmma::matrix_b, 16, 16, 16, __half, wmma::row_major> bf[2];
#pragma unroll
        for (int i = 0; i < 2; i++)
            wmma::load_matrix_sync(af[i], &xh[(wr * 32 + i * 16) * XH_LD + kk], XH_LD);
#pragma unroll
        for (int j = 0; j < 2; j++)
            wmma::load_matrix_sync(bf[j], &wh[kk * W_LD + wc * 32 + j * 16], W_LD);
#pragma unroll
        for (int i = 0; i < 2; i++)
#pragma unroll
            for (int j = 0; j < 2; j++)
                wmma::mma_sync(cf[i][j], af[i], bf[j], cf[i][j]);
    }

    __half* dstBase = (wc < 2) ? g_xlh : g_xrh;
    int colBase = (wc < 2) ? wc * 32 : wc * 32 - 64;
#pragma unroll
    for (int i = 0; i < 2; i++) {
        int gr = nodeBase + wr * 32 + i * 16;
#pragma unroll
        for (int j = 0; j < 2; j++)
            wmma::store_matrix_sync(&dstBase[(size_t)gr * DD + colBase + j * 16],
                                    cf[i][j], DD, wmma::mem_row_major);
    }
}

// ------------------------- CSR build ----------------------------------------
__global__ __launch_bounds__(SCAN_BLK) void k_scan1(int n) {
    __shared__ int sh[SCAN_BLK];
    __shared__ int dh[512];
    int blk = blockIdx.x;
    int base = blk * SCAN_TILE + threadIdx.x * SCAN_ELEM;
    int t = threadIdx.x;
    dh[t] = 0;
    __syncthreads();

    int v[SCAN_ELEM];
    int sum = 0;
#pragma unroll
    for (int i = 0; i < SCAN_ELEM; i++) {
        int idx = base + i;
        v[i] = (idx < n) ? g_cnt[idx] : 0;
        if (idx < n) {
            g_cnt[idx] = 0;
            int bin = v[i] < 511 ? v[i] : 511;
            atomicAdd(&dh[bin], 1);
        }
        sum += v[i];
    }
    sh[t] = sum;
    __syncthreads();
    for (int o = 1; o < SCAN_BLK; o <<= 1) {
        int x = (t >= o) ? sh[t - o] : 0;
        __syncthreads();
        sh[t] += x;
        __syncthreads();
    }
    int run = (t > 0) ? sh[t - 1] : 0;
    if (t == SCAN_BLK - 1) {
        int total = sh[SCAN_BLK - 1];
        for (int j = blk + 1; j < gridDim.x; j++) atomicAdd(&g_pre[j], total);
    }
#pragma unroll
    for (int i = 0; i < SCAN_ELEM; i++) {
        int idx = base + i;
        if (idx < n) { g_rowptr[idx] = run; g_ofs[idx] = run; }
        if (idx == n - 1) g_rowptr[n] = run + v[i];
        run += v[i];
    }
    int c = dh[t];
    if (c) atomicAdd(&g_dhist[t], c);
}

// Fused: degscan (per-block smem scan) + block-aggregated degscatter +
// edge scatter. Blocks [0, nDeg) sort nodes; blocks [nDeg, ...) scatter edges.
__global__ __launch_bounds__(256) void k_csr2(const int* __restrict__ ei,
                                              int E, int n, int nDeg) {
    int t = threadIdx.x;
    if ((int)blockIdx.x < nDeg) {
        __shared__ int sb[512];     // exclusive scan of g_dhist
        __shared__ int ps[256];     // pair sums for the scan
        __shared__ int lh[512];     // local bin counts -> running ranks
        __shared__ int lbase[512];  // reserved global chunk base per bin

        // load + pairwise scan of the 512-bin histogram
        int a = g_dhist[2 * t];
        int b = g_dhist[2 * t + 1];
        ps[t] = a + b;
        lh[t] = 0; lh[t + 256] = 0;
        __syncthreads();
        for (int o = 1; o < 256; o <<= 1) {
            int x = (t >= o) ? ps[t - o] : 0;
            __syncthreads();
            ps[t] += x;
            __syncthreads();
        }
        int pe = (t > 0) ? ps[t - 1] : 0;
        sb[2 * t] = pe;
        sb[2 * t + 1] = pe + a;
        __syncthreads();

        int d = blockIdx.x * 256 + t;
        int bin = -1;
        if (d < n) {
            int deg = (g_rowptr[d + 1] + __ldg(&g_pre[(d + 1) >> 12]))
                    - (g_rowptr[d] + __ldg(&g_pre[d >> 12]));
            bin = deg < 511 ? deg : 511;
            atomicAdd(&lh[bin], 1);
        }
        __syncthreads();

#pragma unroll
        for (int bb = t; bb < 512; bb += 256) {
            int c = lh[bb];
            lbase[bb] = c ? (sb[bb] + atomicAdd(&g_dbase[bb], c)) : 0;
            lh[bb] = 0;
        }
        __syncthreads();

        if (d < n) {
            int r = atomicAdd(&lh[bin], 1);
            g_perm[lbase[bin] + r] = d;
        }
    } else {
        int e = ((int)blockIdx.x - nDeg) * 256 + t;
        if (e < E) {
            int d = ei[E + e];
            int pos = atomicAdd(&g_ofs[d], 1) + __ldg(&g_pre[d >> 12]);
            g_ssrc[pos] = ei[e];
        }
    }
}

// ---------------------------------------------------------------------------
// Fused aggregation: 8 lanes/node, 8 ch/lane, 4 nodes/warp (degree-sorted).
// Chunk of 8 edges fully unrolled: 8 predicated batched LDG.128 (MLP=8).
// ---------------------------------------------------------------------------
__global__ __launch_bounds__(256) void k_agg(const float* __restrict__ xres,
                                             const float* __restrict__ att,
                                             const float* __restrict__ bias,
                                             const float* __restrict__ gamma,
                                             const float* __restrict__ beta,
                                             float* __restrict__ out, int n) {
    int warp = (blockIdx.x * blockDim.x + threadIdx.x) >> 5;
    int lane = threadIdx.x & 31;
    int seg = lane >> 3;
    int l8 = lane & 7;
    int slot = warp * 4 + seg;
    if (slot >= n) return;
    int d = g_perm[slot];
    unsigned m8 = 0xFFu << (seg * 8);
    int j = l8 * 8;

    __half2 xr[4], a6[4], a4[4];
    {
        uint4 rawr = *(const uint4*)&g_xrh[(size_t)d * DD + j];
        xr[0] = *(__half2*)&rawr.x;
        xr[1] = *(__half2*)&rawr.y;
        xr[2] = *(__half2*)&rawr.z;
        xr[3] = *(__half2*)&rawr.w;
        float4 u0 = *(const float4*)(att + j);
        float4 u1 = *(const float4*)(att + j + 4);
        a6[0] = __floats2half2_rn(0.6f * u0.x, 0.6f * u0.y);
        a6[1] = __floats2half2_rn(0.6f * u0.z, 0.6f * u0.w);
        a6[2] = __floats2half2_rn(0.6f * u1.x, 0.6f * u1.y);
        a6[3] = __floats2half2_rn(0.6f * u1.z, 0.6f * u1.w);
        a4[0] = __floats2half2_rn(0.4f * u0.x, 0.4f * u0.y);
        a4[1] = __floats2half2_rn(0.4f * u0.z, 0.4f * u0.w);
        a4[2] = __floats2half2_rn(0.4f * u1.x, 0.4f * u1.y);
        a4[3] = __floats2half2_rn(0.4f * u1.z, 0.4f * u1.w);
    }

    __half2 acc[4];
    acc[0] = acc[1] = acc[2] = acc[3] = __float2half2_rn(0.f);
    float den = 0.f;

    // self loop
    {
        uint4 raw = *(const uint4*)&g_xlh[(size_t)d * DD + j];
        __half2 a0 = *(__half2*)&raw.x, a1 = *(__half2*)&raw.y;
        __half2 a2 = *(__half2*)&raw.z, a3 = *(__half2*)&raw.w;
        __half2 m0 = __hadd2(a0, xr[0]), m1 = __hadd2(a1, xr[1]);
        __half2 m2 = __hadd2(a2, xr[2]), m3 = __hadd2(a3, xr[3]);
        __half2 tt = __hmul2(__habs2(m0), a4[0]);
        tt = __hfma2(m0, a6[0], tt);
        tt = __hfma2(__habs2(m1), a4[1], tt);
        tt = __hfma2(m1, a6[1], tt);
        tt = __hfma2(__habs2(m2), a4[2], tt);
        tt = __hfma2(m2, a6[2], tt);
        tt = __hfma2(__habs2(m3), a4[3], tt);
        tt = __hfma2(m3, a6[3], tt);
        float2 pf = __half22float2(tt);
        float part = pf.x + pf.y;
        part += __shfl_xor_sync(m8, part, 1, 8);
        float p = __expf(part);
        __half2 ph = __float2half2_rn(p);
        acc[0] = __hfma2(ph, a0, acc[0]);
        acc[1] = __hfma2(ph, a1, acc[1]);
        acc[2] = __hfma2(ph, a2, acc[2]);
        acc[3] = __hfma2(ph, a3, acc[3]);
        den += p;
    }

    int pre0 = __ldg(&g_pre[d >> 12]);
    int pre1 = __ldg(&g_pre[(d + 1) >> 12]);
    int begin = g_rowptr[d] + pre0;
    int end = g_rowptr[d + 1] + pre1;

    int svNext = (begin + l8 < end) ? g_ssrc[begin + l8] : 0;

    for (int base = begin; base < end; base += 8) {
        int sv = svNext;
        int nidx = base + 8 + l8;
        svNext = (nidx < end) ? g_ssrc[nidx] : 0;
        int cnt = end - base;
        if (cnt > 8) cnt = 8;

        // batched predicated gather: up to 8 independent LDG.128
        uint4 raw[8];
#pragma unroll
        for (int k = 0; k < 8; k++) {
            int s = __shfl_sync(m8, sv, k, 8);
            raw[k] = make_uint4(0u, 0u, 0u, 0u);
            if (k < cnt) raw[k] = *(const uint4*)&g_xlh[(size_t)s * DD + j];
        }

#pragma unroll
        for (int k = 0; k < 8; k++) {
            __half2 a0 = *(__half2*)&raw[k].x, a1 = *(__half2*)&raw[k].y;
            __half2 a2 = *(__half2*)&raw[k].z, a3 = *(__half2*)&raw[k].w;
            __half2 m0 = __hadd2(a0, xr[0]), m1 = __hadd2(a1, xr[1]);
            __half2 m2 = __hadd2(a2, xr[2]), m3 = __hadd2(a3, xr[3]);
            __half2 tt = __hmul2(__habs2(m0), a4[0]);
            tt = __hfma2(m0, a6[0], tt);
            tt = __hfma2(__habs2(m1), a4[1], tt);
            tt = __hfma2(m1, a6[1], tt);
            tt = __hfma2(__habs2(m2), a4[2], tt);
            tt = __hfma2(m2, a6[2], tt);
            tt = __hfma2(__habs2(m3), a4[3], tt);
            tt = __hfma2(m3, a6[3], tt);
            float2 pf = __half22float2(tt);
            float part = pf.x + pf.y;
            part += __shfl_xor_sync(m8, part, 1, 8);
            float p = (k < cnt) ? __expf(part) : 0.f;
            __half2 ph = __float2half2_rn(p);
            acc[0] = __hfma2(ph, a0, acc[0]);
            acc[1] = __hfma2(ph, a1, acc[1]);
            acc[2] = __hfma2(ph, a2, acc[2]);
            acc[3] = __hfma2(ph, a3, acc[3]);
            den += p;
        }
    }

    // normalize + bias + residual (fp32 epilogue)
    float inv = 1.f / den;
    float v[8];
    {
        float2 f0 = __half22float2(acc[0]);
        float2 f1 = __half22float2(acc[1]);
        float2 f2 = __half22float2(acc[2]);
        float2 f3 = __half22float2(acc[3]);
        float fa[8] = {f0.x, f0.y, f1.x, f1.y, f2.x, f2.y, f3.x, f3.y};
        float4 x0 = *(const float4*)&xres[(size_t)d * DD + j];
        float4 x1 = *(const float4*)&xres[(size_t)d * DD + j + 4];
        float4 b0 = *(const float4*)(bias + j);
        float4 b1 = *(const float4*)(bias + j + 4);
        float xv[8] = {x0.x, x0.y, x0.z, x0.w, x1.x, x1.y, x1.z, x1.w};
        float bi[8] = {b0.x, b0.y, b0.z, b0.w, b1.x, b1.y, b1.z, b1.w};
#pragma unroll
        for (int c = 0; c < 8; c++) v[c] = fa[c] * inv + bi[c] + xv[c];
    }

    float s = 0.f, s2 = 0.f;
#pragma unroll
    for (int c = 0; c < 8; c++) { s += v[c]; s2 += v[c] * v[c]; }
#pragma unroll
    for (int o = 4; o; o >>= 1) {
        s += __shfl_xor_sync(m8, s, o, 8);
        s2 += __shfl_xor_sync(m8, s2, o, 8);
    }
    float mu = s * (1.f / 64.f);
    float var = s2 * (1.f / 64.f) - mu * mu;
    float rstd = rsqrtf(var + 1e-5f);

    float4 g0 = *(const float4*)(gamma + j);
    float4 g1 = *(const float4*)(gamma + j + 4);
    float4 e0 = *(const float4*)(beta + j);
    float4 e1 = *(const float4*)(beta + j + 4);
    float ga[8] = {g0.x, g0.y, g0.z, g0.w, g1.x, g1.y, g1.z, g1.w};
    float be[8] = {e0.x, e0.y, e0.z, e0.w, e1.x, e1.y, e1.z, e1.w};

    const float ks = 0.70710678118654752f;
    float y[8];
#pragma unroll
    for (int c = 0; c < 8; c++) {
        float t = (v[c] - mu) * rstd * ga[c] + be[c];
        y[c] = 0.5f * t * (1.f + erff(t * ks));
    }

    *(float4*)&out[(size_t)d * DD + j] = make_float4(y[0], y[1], y[2], y[3]);
    *(float4*)&out[(size_t)d * DD + j + 4] = make_float4(y[4], y[5], y[6], y[7]);
}

// ---------------------------------------------------------------------------
extern "C" void kernel_launch(void* const* d_in, const int* in_sizes, int n_in,
                              void* d_out, int out_size) {
    const float* x = (const float*)d_in[0];
    const int* ei = (const int*)d_in[1];   // int32: [src(E), dst(E)]
    const float* Wl = (const float*)d_in[2];
    const float* Wr = (const float*)d_in[3];
    const float* att = (const float*)d_in[4];
    const float* bias = (const float*)d_in[5];
    const float* gamma = (const float*)d_in[6];
    const float* beta = (const float*)d_in[7];

    int n = in_sizes[0] / DD;
    int E = in_sizes[1] / 2;
    int Lnum = in_sizes[2] / (DD * DD);

    float *b0p = nullptr, *b1p = nullptr;
    cudaGetSymbolAddress((void**)&b0p, g_b0);
    cudaGetSymbolAddress((void**)&b1p, g_b1);

    const int gemmSmem = 64 * XH_LD * 2 + 64 * W_LD * 2;  // 26624

    static int attr_set = 0;
    if (!attr_set) {
        cudaFuncSetAttribute(k_gemm, cudaFuncAttributeMaxDynamicSharedMemorySize, gemmSmem);
        cudaFuncSetAttribute(k_agg, cudaFuncAttributePreferredSharedMemoryCarveout, 0);
        attr_set = 1;
    }

    int nbScan = (n + SCAN_TILE - 1) / SCAN_TILE;
    int nDeg = (n + 255) / 256;
    int nEdgeBlk = (E + 255) / 256;
    const float* cur = x;
    int aggBlocks = (n + 31) / 32;

    for (int i = 0; i < Lnum; i++) {
        // layer-0 order: gemm+hist(0), scan1(1), csr2(2), agg(3)
        k_gemm<<<(n + 63) / 64, 256, gemmSmem>>>(cur, Wl + (size_t)i * DD * DD,
                                                 Wr + (size_t)i * DD * DD, n,
                                                 ei, E, i == 0 ? 1 : 0);
        if (i == 0) {
            k_scan1<<<nbScan, SCAN_BLK>>>(n);
            k_csr2<<<nDeg + nEdgeBlk, 256>>>(ei, E, n, nDeg);
        }

        float* outp;
        if (i == Lnum - 1) outp = (float*)d_out;
        else outp = (i & 1) ? b1p : b0p;

        k_agg<<<aggBlocks, 256>>>(cur, att + (size_t)i * DD,
                                  bias + (size_t)i * DD,
                                  gamma + (size_t)i * DD,
                                  beta + (size_t)i * DD,
                                  outp, n);
        cur = outp;
    }
}